// round 14
// baseline (speedup 1.0000x reference)
#include <cuda_runtime.h>
#include <math.h>

#define N_SAMPLES   65536
#define N_FRAMES    128
#define NUM_COEFF   6
#define NUM_ACTIVE  7
#define NSER        7
#define NSTAGE      5          // staging slots (4 cp.async groups in flight)
#define HALF        96         // threads per half (3 warps each)
#define KS_THREADS  192        // 6 warps: plain half + expanded half
#define TILE_MAX    768

// ---------------- device scratch (no allocation allowed) ----------------
__device__ float  g_y[NSER][N_FRAMES];
__device__ float  g_M[NSER][N_FRAMES];
// pass-1 per-sample data (u = reference vals, NEGATIVE weights)
__device__ float4 g_U1[N_SAMPLES];
__device__ float4 g_U2[N_SAMPLES];       // u4,u5,u6, x
__device__ int    g_p[N_SAMPLES];        // p_t = t - 1 - z_t
// plain 8-wide windows (R8 format: shift-folded weights)
__device__ float4 g_A[N_SAMPLES];
__device__ float4 g_B[N_SAMPLES];
__device__ float2 g_C[N_SAMPLES];        // (x, bitcast high-copy base w8)
// 16-wide windows (plain-or-expanded per offset)
__device__ float4 g_W0[N_SAMPLES];
__device__ float4 g_W1[N_SAMPLES];
__device__ float4 g_W2[N_SAMPLES];
__device__ float4 g_W3[N_SAMPLES];
__device__ float2 g_D[N_SAMPLES];        // (x_tilde, bitcast low-copy base B)
__device__ int    g_minz;
__device__ int    g_maxz;
__device__ int    g_flag;
__device__ int    g_spanbad;

// mode helper (identical everywhere)
__device__ __forceinline__ void ks_mode(int minz, int maxz, int spanbad,
                                        int& L1, int& L, bool& mode2)
{
    L1 = minz + 1;
    if (L1 > HALF) L1 = HALF;
    int cap1 = 1023 - maxz - NUM_ACTIVE - 1;
    if (L1 > cap1) L1 = cap1;
    if (L1 < 1)  L1 = 1;
    bool noexp = (2 * maxz + 16 + 2 * L1 > 1020);
    mode2 = !(noexp || spanbad);
    L = mode2 ? 2 * L1 : L1;
}
__device__ __forceinline__ bool ks_noexp(int minz, int maxz, int L1)
{
    return (2 * maxz + 16 + 2 * L1 > 1020);
}

// ---------------- kernel A: coeff frames + spline tridiagonal solves -------
__global__ void prep_kernel(const float* __restrict__ delay,
                            const float* __restrict__ raw_gain,
                            const float* __restrict__ raw_coeff)
{
    __shared__ float s_y[NSER][N_FRAMES];
    __shared__ float s_cp[N_FRAMES];
    __shared__ float s_d[NSER][N_FRAMES];
    __shared__ float s_gain;

    const int tid = threadIdx.x;

    if (tid == 0) {
        s_gain = 1.0f / (1.0f + expf(-raw_gain[0]));
        g_minz = 0x7fffffff;
        g_maxz = 0;
        g_flag = 0;
        g_spanbad = 0;
        float c = 0.25f;
        s_cp[0] = c;
        for (int i = 1; i < N_FRAMES - 2; i++) {
            c = 1.0f / (4.0f - c);
            s_cp[i] = c;
        }
    }
    __syncthreads();

    for (int i = tid; i < N_FRAMES * NUM_COEFF; i += blockDim.x) {
        int r = i / NUM_COEFF, c = i % NUM_COEFF;
        s_y[1 + c][r] = 1.0f / (1.0f + expf(-raw_coeff[i]));
    }
    for (int r = tid; r < N_FRAMES; r += blockDim.x)
        s_y[0][r] = delay[r];
    __syncthreads();

    for (int r = tid; r < N_FRAMES; r += blockDim.x) {
        float sum = 0.0f;
        #pragma unroll
        for (int c = 0; c < NUM_COEFF; c++) sum += s_y[1 + c][r];
        float scale = s_gain / sum;
        #pragma unroll
        for (int c = 0; c < NUM_COEFF; c++) s_y[1 + c][r] *= scale;
    }
    __syncthreads();

    if (tid < NSER) {
        const int m = N_FRAMES - 2;
        const float K = 6.0f * 127.0f * 127.0f;
        float* y = s_y[tid];
        float* d = s_d[tid];

        float dp = K * (y[2] - 2.0f * y[1] + y[0]) * 0.25f;
        d[0] = dp;
        for (int i = 1; i < m; i++) {
            float rhs = K * (y[i + 2] - 2.0f * y[i + 1] + y[i]);
            dp = (rhs - dp) * s_cp[i];
            d[i] = dp;
        }
        g_M[tid][0] = 0.0f;
        g_M[tid][N_FRAMES - 1] = 0.0f;
        float Mn = 0.0f;
        for (int i = m - 1; i >= 0; i--) {
            Mn = d[i] - s_cp[i] * Mn;
            g_M[tid][i + 1] = Mn;
        }
    }
    __syncthreads();

    for (int i = tid; i < NSER * N_FRAMES; i += blockDim.x)
        (&g_y[0][0])[i] = (&s_y[0][0])[i];
}

// ---------------- kernel B: spline eval -> u, p, x  AND plain 8-wide window
__global__ void sample_kernel(const float* __restrict__ exc,
                              const float* __restrict__ burst)
{
    const int t = blockIdx.x * blockDim.x + threadIdx.x;
    if (t >= N_SAMPLES) return;

    const float tt = (float)t * (1.0f / 65535.0f);
    int idx = (int)floorf(tt * 127.0f);
    idx = max(0, min(idx, 126));
    const float s  = tt - (float)idx * (1.0f / 127.0f);
    const float s2 = s * s;
    const float s3 = s2 * s;

    float vout[NSER];
    #pragma unroll
    for (int c = 0; c < NSER; c++) {
        float yi  = g_y[c][idx];
        float yi1 = g_y[c][idx + 1];
        float Mi  = g_M[c][idx];
        float Mi1 = g_M[c][idx + 1];
        float bsl = (yi1 - yi) * 127.0f - (2.0f * Mi + Mi1) * (1.0f / 762.0f);
        vout[c] = yi + bsl * s + 0.5f * Mi * s2 + (Mi1 - Mi) * s3 * (127.0f / 6.0f);
    }

    const float delay_i = vout[0];
    const int   z    = (int)floorf(delay_i);
    const float alfa = delay_i - (float)z;
    const float oma  = 1.0f - alfa;

    // u = vals (pre-negated, reference form): y = x - sum u[k]*y[p-k]
    float u[7];
    u[0] = -oma * vout[1];
    #pragma unroll
    for (int k = 1; k < NUM_COEFF; k++)
        u[k] = -(alfa * vout[k] + oma * vout[k + 1]);
    u[6] = -alfa * vout[NUM_COEFF];

    const float x = burst[t];
    g_U1[t] = make_float4(u[0], u[1], u[2], u[3]);
    g_U2[t] = make_float4(u[4], u[5], u[6], x);
    g_p[t]  = t - 1 - z;

    // plain 8-wide (shift-folded) window, R8 format
    const int pbH = ((t - 1 - z) & 1023) + 1024;
    const int d   = (pbH - 6) & 1;
    const int w8  = (pbH - 6) & ~1;
    float w[8];
    #pragma unroll
    for (int i = 0; i < 8; i++) w[i] = 0.0f;
    #pragma unroll
    for (int k = 0; k < 7; k++) w[6 + d - k] = u[k];
    g_A[t] = make_float4(w[0], w[1], w[2], w[3]);
    g_B[t] = make_float4(w[4], w[5], w[6], w[7]);
    g_C[t] = make_float2(x, __int_as_float(w8));

    if (exc[t] != 0.0f) atomicExch(&g_flag, 1);

    int wmin = __reduce_min_sync(0xffffffffu, z);
    int wmax = __reduce_max_sync(0xffffffffu, z);
    if ((threadIdx.x & 31) == 0) {
        atomicMin(&g_minz, wmin);
        atomicMax(&g_maxz, wmax);
    }
}

// ---------------- kernel B2: general exc IIR fallback ----------------------
__global__ void exc_scan_kernel(const float* __restrict__ exc,
                                const float* __restrict__ burst)
{
    if (g_flag) {
        float ym1 = 0.0f;
        for (int t = 0; t < N_SAMPLES; t++) {
            ym1 = burst[t] - exc[t] * ym1;
            g_U2[t].w = ym1;
            g_C[t].x  = ym1;
        }
    }
}

// ---------------- kernel B3: build 16-tap dense windows (verified R10) -----
__global__ void expand_kernel()
{
    __shared__ float4 sU1[TILE_MAX];
    __shared__ float4 sU2[TILE_MAX];
    __shared__ int    sP [TILE_MAX];

    const int tid = threadIdx.x;
    const int t0  = blockIdx.x * blockDim.x;
    const int t   = t0 + tid;

    const int minz = g_minz, maxz = g_maxz;
    int L1, Ld; bool m2d;
    ks_mode(minz, maxz, 0, L1, Ld, m2d);
    const bool noexp = ks_noexp(minz, maxz, L1);
    const int  L2 = 2 * L1;

    int R = 0;
    if (!noexp) {
        R = maxz + 8;
        const int tileN = R + (int)blockDim.x;
        for (int i = tid; i < tileN; i += blockDim.x) {
            int tg = t0 - R + i;
            if (tg >= 0 && tg < N_SAMPLES) {
                sU1[i] = g_U1[tg];
                sU2[i] = g_U2[tg];
                sP [i] = g_p[tg];
            } else {
                sU1[i] = make_float4(0, 0, 0, 0);
                sU2[i] = make_float4(0, 0, 0, 0);
                sP [i] = 0;
            }
        }
        __syncthreads();
    }

    if (t >= N_SAMPLES) return;

    float4 U1, U2; int p;
    if (!noexp) { U1 = sU1[R + tid]; U2 = sU2[R + tid]; p = sP[R + tid]; }
    else        { U1 = g_U1[t];      U2 = g_U2[t];      p = g_p[t]; }

    float u[7] = {U1.x, U1.y, U1.z, U1.w, U2.x, U2.y, U2.z};
    float x    = U2.w;

    float W[16];
    #pragma unroll
    for (int i = 0; i < 16; i++) W[i] = 0.0f;
    float xt = x;
    int   wbase = 0;

    const int o = t % L2;
    bool expanded = (!noexp) && (o >= L1);
    bool plain = !expanded;

    if (expanded) {
        int pmin = 0x7fffffff, pmax = -0x7fffffff;
        #pragma unroll
        for (int k = 0; k < 7; k++) {
            int tau = p - k;
            if (tau < 0) continue;
            int pt = sP[tau - t0 + R];
            pmin = min(pmin, pt);
            pmax = max(pmax, pt);
        }
        if (pmin > pmax) {
            wbase = 0;        // all taps hit y[<0] = 0:  y = x
        } else {
            wbase = (pmin - 6) & ~1;
            if (pmax - wbase > 15) {
                atomicExch(&g_spanbad, 1);
                plain = true;
            } else {
                #pragma unroll
                for (int k = 0; k < 7; k++) {
                    int tau = p - k;
                    if (tau < 0) continue;
                    const int ti = tau - t0 + R;
                    const float uk = u[k];
                    float4 V1 = sU1[ti];
                    float4 V2 = sU2[ti];
                    int    pt = sP[ti];
                    xt -= uk * V2.w;
                    const int b = pt - wbase;
                    W[b    ] -= uk * V1.x;
                    W[b - 1] -= uk * V1.y;
                    W[b - 2] -= uk * V1.z;
                    W[b - 3] -= uk * V1.w;
                    W[b - 4] -= uk * V2.x;
                    W[b - 5] -= uk * V2.y;
                    W[b - 6] -= uk * V2.z;
                }
            }
        }
    }

    if (plain) {
        wbase = (p - 6) & ~1;
        xt = x;
        #pragma unroll
        for (int i = 0; i < 16; i++) W[i] = 0.0f;
        #pragma unroll
        for (int k = 0; k < 7; k++)
            W[p - k - wbase] = u[k];
    }

    g_W0[t] = make_float4(W[0],  W[1],  W[2],  W[3]);
    g_W1[t] = make_float4(W[4],  W[5],  W[6],  W[7]);
    g_W2[t] = make_float4(W[8],  W[9],  W[10], W[11]);
    g_W3[t] = make_float4(W[12], W[13], W[14], W[15]);
    const int B = (int)(((unsigned)wbase) & 1023u);
    g_D[t] = make_float2(xt, __int_as_float(B));
}

// ---------------- cp.async helpers ----------------
__device__ __forceinline__ void cpa16(void* dst_smem, const void* src) {
    unsigned d = (unsigned)__cvta_generic_to_shared(dst_smem);
    asm volatile("cp.async.ca.shared.global [%0], [%1], 16;"
                 :: "r"(d), "l"(src) : "memory");
}
__device__ __forceinline__ void cpa8(void* dst_smem, const void* src) {
    unsigned d = (unsigned)__cvta_generic_to_shared(dst_smem);
    asm volatile("cp.async.ca.shared.global [%0], [%1], 8;"
                 :: "r"(d), "l"(src) : "memory");
}

// ---------------- smem staging layout (dynamic) ----------------------------
#define OFF_A    8192
#define OFF_B    (OFF_A  + NSTAGE * HALF * 16)
#define OFF_C    (OFF_B  + NSTAGE * HALF * 16)
#define OFF_W0   (OFF_C  + NSTAGE * HALF * 8)
#define OFF_W1   (OFF_W0 + NSTAGE * HALF * 16)
#define OFF_W2   (OFF_W1 + NSTAGE * HALF * 16)
#define OFF_W3   (OFF_W2 + NSTAGE * HALF * 16)
#define OFF_D    (OFF_W3 + NSTAGE * HALF * 16)
#define DYN_TOT  (OFF_D  + NSTAGE * HALF * 8)

// ---------------- kernel C: warp-split asymmetric double-chunk KS scan -----
// mode2: chunk = L2 = 2*L1.  Warps 0-2 (tid<96) handle the plain half
// (offset tid, 8-wide window); warps 3-5 handle the expanded half
// (offset L1+(tid-96), 16-wide window) CONCURRENTLY — the two LSU chains
// live on different warps and overlap via SMT instead of serializing in one
// thread (R13's failure).  Both halves read strictly BEFORE the chunk start
// (plain: o-1-minz<0; expanded: two-hop taps < c*L2), so one barrier per
// iteration suffices and intra-iteration order is free.  Ring span <=
// L2+2*maxz+16 <= 1020 (ks_mode), dup-ring / zero-slot arguments as before.
// fallback: uniform 16-wide at L1 using threads 0-95 (all threads barrier).
__global__ void __launch_bounds__(KS_THREADS, 1) ks_kernel(float* __restrict__ out)
{
    extern __shared__ char dyn[];
    float*  ring = (float*)dyn;
    float4* sA  = (float4*)(dyn + OFF_A);
    float4* sB  = (float4*)(dyn + OFF_B);
    float2* sC  = (float2*)(dyn + OFF_C);
    float4* sW0 = (float4*)(dyn + OFF_W0);
    float4* sW1 = (float4*)(dyn + OFF_W1);
    float4* sW2 = (float4*)(dyn + OFF_W2);
    float4* sW3 = (float4*)(dyn + OFF_W3);
    float2* sD  = (float2*)(dyn + OFF_D);
    __shared__ int sL1, sM2;

    const int tid = threadIdx.x;
    #pragma unroll
    for (int i = tid; i < 2048; i += KS_THREADS) ring[i] = 0.0f;

    if (tid == 0) {
        int L1, L; bool m2;
        ks_mode(g_minz, g_maxz, g_spanbad, L1, L, m2);
        sL1 = L1;
        sM2 = m2 ? 1 : 0;
    }
    __syncthreads();
    const int  L1 = sL1;
    const bool m2 = (sM2 != 0);

    if (m2) {
        // ===== mode2: L2 chunks; plain half on warps 0-2, expanded on 3-5 ==
        const int  L2 = 2 * L1;
        const int  nIter = (N_SAMPLES + L2 - 1) / L2;
        const bool isPlain = (tid < HALF);
        const int  ti = isPlain ? tid : (tid - HALF);
        const bool on = (ti < L1);

        // prologue: iterations 0..3 -> slots 0..3
        #pragma unroll
        for (int s = 0; s < NSTAGE - 1; s++) {
            if (isPlain) {
                const int t1 = s * L2 + ti;
                if (on && t1 < N_SAMPLES) {
                    cpa16(&sA[s * HALF + ti], &g_A[t1]);
                    cpa16(&sB[s * HALF + ti], &g_B[t1]);
                    cpa8 (&sC[s * HALF + ti], &g_C[t1]);
                }
            } else {
                const int t2 = s * L2 + L1 + ti;
                if (on && t2 < N_SAMPLES) {
                    cpa16(&sW0[s * HALF + ti], &g_W0[t2]);
                    cpa16(&sW1[s * HALF + ti], &g_W1[t2]);
                    cpa16(&sW2[s * HALF + ti], &g_W2[t2]);
                    cpa16(&sW3[s * HALF + ti], &g_W3[t2]);
                    cpa8 (&sD [s * HALF + ti], &g_D[t2]);
                }
            }
            asm volatile("cp.async.commit_group;" ::: "memory");
        }

        for (int c0 = 0; c0 < nIter; c0 += NSTAGE) {
            #pragma unroll
            for (int s = 0; s < NSTAGE; s++) {
                const int c = c0 + s;
                if (c < nIter) {
                    asm volatile("cp.async.wait_group 3;" ::: "memory");
                    const int s4 = (s + NSTAGE - 1) % NSTAGE;

                    if (isPlain) {
                        const float2 cc = sC[s * HALF + ti];
                        const float4 a  = sA[s * HALF + ti];
                        const float4 b  = sB[s * HALF + ti];

                        const int tp1 = (c + NSTAGE - 1) * L2 + ti;
                        if (on && tp1 < N_SAMPLES) {
                            cpa16(&sA[s4 * HALF + ti], &g_A[tp1]);
                            cpa16(&sB[s4 * HALF + ti], &g_B[tp1]);
                            cpa8 (&sC[s4 * HALF + ti], &g_C[tp1]);
                        }
                        asm volatile("cp.async.commit_group;" ::: "memory");

                        const int t1 = c * L2 + ti;
                        if (on && t1 < N_SAMPLES) {
                            const int w8 = __float_as_int(cc.y);
                            float2 f0 = *reinterpret_cast<const float2*>(&ring[w8    ]);
                            float2 f1 = *reinterpret_cast<const float2*>(&ring[w8 + 2]);
                            float2 f2 = *reinterpret_cast<const float2*>(&ring[w8 + 4]);
                            float2 f3 = *reinterpret_cast<const float2*>(&ring[w8 + 6]);
                            float m0 = fmaf(a.x, f0.x, a.y * f0.y);
                            float m1 = fmaf(a.z, f1.x, a.w * f1.y);
                            float m2_ = fmaf(b.x, f2.x, b.y * f2.y);
                            float m3 = fmaf(b.z, f3.x, b.w * f3.y);
                            float y  = cc.x - ((m0 + m1) + (m2_ + m3));
                            const int slot = t1 & 1023;
                            ring[slot]        = y;
                            ring[slot + 1024] = y;
                            out[t1] = y;
                        }
                    } else {
                        const float2 dd = sD [s * HALF + ti];
                        const float4 w0 = sW0[s * HALF + ti];
                        const float4 w1 = sW1[s * HALF + ti];
                        const float4 w2 = sW2[s * HALF + ti];
                        const float4 w3 = sW3[s * HALF + ti];

                        const int tp2 = (c + NSTAGE - 1) * L2 + L1 + ti;
                        if (on && tp2 < N_SAMPLES) {
                            cpa16(&sW0[s4 * HALF + ti], &g_W0[tp2]);
                            cpa16(&sW1[s4 * HALF + ti], &g_W1[tp2]);
                            cpa16(&sW2[s4 * HALF + ti], &g_W2[tp2]);
                            cpa16(&sW3[s4 * HALF + ti], &g_W3[tp2]);
                            cpa8 (&sD [s4 * HALF + ti], &g_D[tp2]);
                        }
                        asm volatile("cp.async.commit_group;" ::: "memory");

                        const int t2 = c * L2 + L1 + ti;
                        if (on && t2 < N_SAMPLES) {
                            const int B = __float_as_int(dd.y);
                            float2 e0 = *reinterpret_cast<const float2*>(&ring[B     ]);
                            float2 e1 = *reinterpret_cast<const float2*>(&ring[B +  2]);
                            float2 e2 = *reinterpret_cast<const float2*>(&ring[B +  4]);
                            float2 e3 = *reinterpret_cast<const float2*>(&ring[B +  6]);
                            float2 e4 = *reinterpret_cast<const float2*>(&ring[B +  8]);
                            float2 e5 = *reinterpret_cast<const float2*>(&ring[B + 10]);
                            float2 e6 = *reinterpret_cast<const float2*>(&ring[B + 12]);
                            float2 e7 = *reinterpret_cast<const float2*>(&ring[B + 14]);
                            float n0 = fmaf(w0.x, e0.x, w0.y * e0.y);
                            float n1 = fmaf(w0.z, e1.x, w0.w * e1.y);
                            float n2 = fmaf(w1.x, e2.x, w1.y * e2.y);
                            float n3 = fmaf(w1.z, e3.x, w1.w * e3.y);
                            float n4 = fmaf(w2.x, e4.x, w2.y * e4.y);
                            float n5 = fmaf(w2.z, e5.x, w2.w * e5.y);
                            float n6 = fmaf(w3.x, e6.x, w3.y * e6.y);
                            float n7 = fmaf(w3.z, e7.x, w3.w * e7.y);
                            float y2 = dd.x - (((n0 + n1) + (n2 + n3)) + ((n4 + n5) + (n6 + n7)));
                            const int slot = t2 & 1023;
                            ring[slot]        = y2;
                            ring[slot + 1024] = y2;
                            out[t2] = y2;
                        }
                    }
                    __syncthreads();
                }
            }
        }
    } else {
        // ===== fallback: L1 chunks, uniform 16-wide, threads 0-95 work =====
        const int  nIter = (N_SAMPLES + L1 - 1) / L1;
        const bool on = (tid < L1);    // tid >= 96 never active, still barriers

        #pragma unroll
        for (int s = 0; s < NSTAGE - 1; s++) {
            const int t = s * L1 + tid;
            if (on && t < N_SAMPLES) {
                cpa16(&sW0[s * HALF + tid], &g_W0[t]);
                cpa16(&sW1[s * HALF + tid], &g_W1[t]);
                cpa16(&sW2[s * HALF + tid], &g_W2[t]);
                cpa16(&sW3[s * HALF + tid], &g_W3[t]);
                cpa8 (&sD [s * HALF + tid], &g_D[t]);
            }
            asm volatile("cp.async.commit_group;" ::: "memory");
        }

        int slot = tid & 1023;

        for (int c0 = 0; c0 < nIter; c0 += NSTAGE) {
            #pragma unroll
            for (int s = 0; s < NSTAGE; s++) {
                const int c = c0 + s;
                if (c < nIter) {
                    asm volatile("cp.async.wait_group 3;" ::: "memory");

                    float2 dd = make_float2(0.0f, 0.0f);
                    float4 w0, w1, w2, w3;
                    if (on) {
                        dd = sD [s * HALF + tid];
                        w0 = sW0[s * HALF + tid];
                        w1 = sW1[s * HALF + tid];
                        w2 = sW2[s * HALF + tid];
                        w3 = sW3[s * HALF + tid];
                    }

                    const int s4 = (s + NSTAGE - 1) % NSTAGE;
                    const int tp = (c + NSTAGE - 1) * L1 + tid;
                    if (on && tp < N_SAMPLES) {
                        cpa16(&sW0[s4 * HALF + tid], &g_W0[tp]);
                        cpa16(&sW1[s4 * HALF + tid], &g_W1[tp]);
                        cpa16(&sW2[s4 * HALF + tid], &g_W2[tp]);
                        cpa16(&sW3[s4 * HALF + tid], &g_W3[tp]);
                        cpa8 (&sD [s4 * HALF + tid], &g_D[tp]);
                    }
                    asm volatile("cp.async.commit_group;" ::: "memory");

                    const int t = c * L1 + tid;
                    if (on && t < N_SAMPLES) {
                        const int B = __float_as_int(dd.y);
                        float2 e0 = *reinterpret_cast<const float2*>(&ring[B     ]);
                        float2 e1 = *reinterpret_cast<const float2*>(&ring[B +  2]);
                        float2 e2 = *reinterpret_cast<const float2*>(&ring[B +  4]);
                        float2 e3 = *reinterpret_cast<const float2*>(&ring[B +  6]);
                        float2 e4 = *reinterpret_cast<const float2*>(&ring[B +  8]);
                        float2 e5 = *reinterpret_cast<const float2*>(&ring[B + 10]);
                        float2 e6 = *reinterpret_cast<const float2*>(&ring[B + 12]);
                        float2 e7 = *reinterpret_cast<const float2*>(&ring[B + 14]);
                        float n0 = fmaf(w0.x, e0.x, w0.y * e0.y);
                        float n1 = fmaf(w0.z, e1.x, w0.w * e1.y);
                        float n2 = fmaf(w1.x, e2.x, w1.y * e2.y);
                        float n3 = fmaf(w1.z, e3.x, w1.w * e3.y);
                        float n4 = fmaf(w2.x, e4.x, w2.y * e4.y);
                        float n5 = fmaf(w2.z, e5.x, w2.w * e5.y);
                        float n6 = fmaf(w3.x, e6.x, w3.y * e6.y);
                        float n7 = fmaf(w3.z, e7.x, w3.w * e7.y);
                        float y  = dd.x - (((n0 + n1) + (n2 + n3)) + ((n4 + n5) + (n6 + n7)));
                        ring[slot]        = y;
                        ring[slot + 1024] = y;
                        out[t] = y;
                    }
                    __syncthreads();

                    slot = (slot + L1) & 1023;
                }
            }
        }
    }
}

// ---------------- launcher ----------------
extern "C" void kernel_launch(void* const* d_in, const int* in_sizes, int n_in,
                              void* d_out, int out_size)
{
    const float* delay     = (const float*)d_in[0];  // [128]
    const float* raw_gain  = (const float*)d_in[1];  // [1]
    const float* raw_coeff = (const float*)d_in[2];  // [128,6]
    const float* exc       = (const float*)d_in[3];  // [1,65536,1]
    const float* burst     = (const float*)d_in[4];  // [65536]
    float* out = (float*)d_out;

    static bool attr_done = false;
    if (!attr_done) {
        cudaFuncSetAttribute(ks_kernel, cudaFuncAttributeMaxDynamicSharedMemorySize, DYN_TOT);
        attr_done = true;
    }

    prep_kernel<<<1, 256>>>(delay, raw_gain, raw_coeff);
    sample_kernel<<<N_SAMPLES / 256, 256>>>(exc, burst);
    exc_scan_kernel<<<1, 1>>>(exc, burst);
    expand_kernel<<<N_SAMPLES / 256, 256>>>();
    ks_kernel<<<1, KS_THREADS, DYN_TOT>>>(out);
}

// round 15
// speedup vs baseline: 1.3501x; 1.3501x over previous
#include <cuda_runtime.h>
#include <math.h>

#define N_SAMPLES   65536
#define N_FRAMES    128
#define NUM_COEFF   6
#define NUM_ACTIVE  7
#define NSER        7
#define NSTAGE      5        // staging slots (4 cp.async groups in flight)
#define KS_THREADS  96       // 3 warps; L capped at 96 so all threads are active

// ---------------- device scratch (no allocation allowed) ----------------
__device__ float  g_y[NSER][N_FRAMES];
__device__ float  g_M[NSER][N_FRAMES];
__device__ float4 g_A[N_SAMPLES];        // shifted weights w0..w3
__device__ float4 g_B[N_SAMPLES];        // shifted weights w4..w7
__device__ float2 g_C[N_SAMPLES];        // (x, bitcast LOW ring window base BL)
__device__ int    g_minz;
__device__ int    g_maxz;
__device__ int    g_flag;

// ---------------- kernel A: coeff frames + spline tridiagonal solves -------
__global__ void prep_kernel(const float* __restrict__ delay,
                            const float* __restrict__ raw_gain,
                            const float* __restrict__ raw_coeff)
{
    __shared__ float s_y[NSER][N_FRAMES];
    __shared__ float s_cp[N_FRAMES];
    __shared__ float s_d[NSER][N_FRAMES];
    __shared__ float s_gain;

    const int tid = threadIdx.x;

    if (tid == 0) {
        s_gain = 1.0f / (1.0f + expf(-raw_gain[0]));
        g_minz = 0x7fffffff;
        g_maxz = 0;
        g_flag = 0;
        float c = 0.25f;
        s_cp[0] = c;
        for (int i = 1; i < N_FRAMES - 2; i++) {
            c = 1.0f / (4.0f - c);
            s_cp[i] = c;
        }
    }
    __syncthreads();

    for (int i = tid; i < N_FRAMES * NUM_COEFF; i += blockDim.x) {
        int r = i / NUM_COEFF, c = i % NUM_COEFF;
        s_y[1 + c][r] = 1.0f / (1.0f + expf(-raw_coeff[i]));
    }
    for (int r = tid; r < N_FRAMES; r += blockDim.x)
        s_y[0][r] = delay[r];
    __syncthreads();

    for (int r = tid; r < N_FRAMES; r += blockDim.x) {
        float sum = 0.0f;
        #pragma unroll
        for (int c = 0; c < NUM_COEFF; c++) sum += s_y[1 + c][r];
        float scale = s_gain / sum;
        #pragma unroll
        for (int c = 0; c < NUM_COEFF; c++) s_y[1 + c][r] *= scale;
    }
    __syncthreads();

    if (tid < NSER) {
        const int m = N_FRAMES - 2;
        const float K = 6.0f * 127.0f * 127.0f;
        float* y = s_y[tid];
        float* d = s_d[tid];

        float dp = K * (y[2] - 2.0f * y[1] + y[0]) * 0.25f;
        d[0] = dp;
        for (int i = 1; i < m; i++) {
            float rhs = K * (y[i + 2] - 2.0f * y[i + 1] + y[i]);
            dp = (rhs - dp) * s_cp[i];
            d[i] = dp;
        }
        g_M[tid][0] = 0.0f;
        g_M[tid][N_FRAMES - 1] = 0.0f;
        float Mn = 0.0f;
        for (int i = m - 1; i >= 0; i--) {
            Mn = d[i] - s_cp[i] * Mn;
            g_M[tid][i + 1] = Mn;
        }
    }
    __syncthreads();

    for (int i = tid; i < NSER * N_FRAMES; i += blockDim.x)
        (&g_y[0][0])[i] = (&s_y[0][0])[i];
}

// ---------------- kernel B: per-sample spline eval + SHIFTED tap weights ---
// Tap positions pb-6..pb (pb = (t-1-z) mod 1024) are read as a contiguous
// aligned 8-float window in a 1040-entry ring whose tail [1024..1039]
// replicates slots [0..15].  Let q = pb-6 (wrapped up by +1024 if negative):
// BL = q & ~1, d = q & 1.  Tap r_k sits at window index 6+d-k, so storing
// w[6+d-k] = v[k] (zero padded) makes the scan a plain 8-FMA dot.
// Windows never exceed index 1039: BL <= 1022, BL+7 <= 1029.
__global__ void sample_kernel(const float* __restrict__ exc,
                              const float* __restrict__ burst)
{
    const int t = blockIdx.x * blockDim.x + threadIdx.x;
    if (t >= N_SAMPLES) return;

    const float tt = (float)t * (1.0f / 65535.0f);
    int idx = (int)floorf(tt * 127.0f);
    idx = max(0, min(idx, 126));
    const float s  = tt - (float)idx * (1.0f / 127.0f);
    const float s2 = s * s;
    const float s3 = s2 * s;

    float vout[NSER];
    #pragma unroll
    for (int c = 0; c < NSER; c++) {
        float yi  = g_y[c][idx];
        float yi1 = g_y[c][idx + 1];
        float Mi  = g_M[c][idx];
        float Mi1 = g_M[c][idx + 1];
        float bsl = (yi1 - yi) * 127.0f - (2.0f * Mi + Mi1) * (1.0f / 762.0f);
        vout[c] = yi + bsl * s + 0.5f * Mi * s2 + (Mi1 - Mi) * s3 * (127.0f / 6.0f);
    }

    const float delay_i = vout[0];
    const int   z    = (int)floorf(delay_i);
    const float alfa = delay_i - (float)z;
    const float oma  = 1.0f - alfa;

    float v[7];
    v[0] = -oma * vout[1];
    #pragma unroll
    for (int k = 1; k < NUM_COEFF; k++)
        v[k] = -(alfa * vout[k] + oma * vout[k + 1]);
    v[6] = -alfa * vout[NUM_COEFF];

    const int pb = (t - 1 - z) & 1023;
    int q = pb - 6;
    if (q < 0) q += 1024;              // wrap-at-top window lands in tail replica
    const int d  = q & 1;
    const int BL = q & ~1;

    float w[8];
    #pragma unroll
    for (int i = 0; i < 8; i++) w[i] = 0.0f;
    #pragma unroll
    for (int k = 0; k < 7; k++) w[6 + d - k] = v[k];

    g_A[t] = make_float4(w[0], w[1], w[2], w[3]);
    g_B[t] = make_float4(w[4], w[5], w[6], w[7]);
    g_C[t] = make_float2(burst[t], __int_as_float(BL));

    if (exc[t] != 0.0f) atomicExch(&g_flag, 1);

    int wmin = __reduce_min_sync(0xffffffffu, z);
    int wmax = __reduce_max_sync(0xffffffffu, z);
    if ((threadIdx.x & 31) == 0) {
        atomicMin(&g_minz, wmin);
        atomicMax(&g_maxz, wmax);
    }
}

// ---------------- kernel B2: general exc IIR fallback ----------------------
__global__ void exc_scan_kernel(const float* __restrict__ exc,
                                const float* __restrict__ burst)
{
    if (g_flag) {
        float ym1 = 0.0f;
        for (int t = 0; t < N_SAMPLES; t++) {
            ym1 = burst[t] - exc[t] * ym1;
            g_C[t].x = ym1;
        }
    }
}

// ---------------- cp.async helpers ----------------
__device__ __forceinline__ void cpa16(void* dst_smem, const void* src) {
    unsigned d = (unsigned)__cvta_generic_to_shared(dst_smem);
    asm volatile("cp.async.ca.shared.global [%0], [%1], 16;"
                 :: "r"(d), "l"(src) : "memory");
}
__device__ __forceinline__ void cpa8(void* dst_smem, const void* src) {
    unsigned d = (unsigned)__cvta_generic_to_shared(dst_smem);
    asm volatile("cp.async.ca.shared.global [%0], [%1], 8;"
                 :: "r"(d), "l"(src) : "memory");
}

// ---------------- kernel C: chunk-parallel Karplus-Strong scan -------------
// R12 champion structure (3 warps, cp.async 5-slot staging, at-use reads,
// cc loaded first) with a SEAM-REPLICATED ring replacing the full duplicate:
// ring[0..1023] + tail [1024..1039] mirroring slots 0..15.  Writers issue
// ONE STS (two only when slot < 16, ~1.6% of writes), halving the pending-
// STS count the per-iteration __syncthreads must drain.  Readers use the
// precomputed low base BL (window [BL, BL+7], BL+7 <= 1029; tail entries
// replicate (i-1024), written by the same thread in the same interval).
// Mod-1024 aliasing / zero-slot / readiness arguments unchanged from R8/R12.
__global__ void __launch_bounds__(KS_THREADS, 1) ks_kernel(float* __restrict__ out)
{
    __shared__ __align__(16) float ring[1056];
    __shared__ float4 stA[NSTAGE][KS_THREADS];
    __shared__ float4 stB[NSTAGE][KS_THREADS];
    __shared__ float2 stC[NSTAGE][KS_THREADS];
    __shared__ int    sL;

    const int tid = threadIdx.x;
    #pragma unroll
    for (int i = tid; i < 1056; i += KS_THREADS) ring[i] = 0.0f;

    if (tid == 0) {
        int L = g_minz + 1;
        if (L > KS_THREADS) L = KS_THREADS;
        int cap = 1024 - (g_maxz + NUM_ACTIVE) - 1;
        if (L > cap) L = cap;
        if (L < 1)  L = 1;
        sL = L;
    }
    __syncthreads();
    const int  L  = sL;
    const bool on = (tid < L);
    const int  nChunks = (N_SAMPLES + L - 1) / L;

    // prologue: chunks 0..3 -> slots 0..3 (4 groups in flight)
    #pragma unroll
    for (int s = 0; s < NSTAGE - 1; s++) {
        const int t = s * L + tid;
        if (on) {
            cpa16(&stA[s][tid], &g_A[t]);
            cpa16(&stB[s][tid], &g_B[t]);
            cpa8 (&stC[s][tid], &g_C[t]);
        }
        asm volatile("cp.async.commit_group;" ::: "memory");
    }

    int    slot = tid & 1023;                  // ring write slot
    float* outp = out + tid;

    for (int c0 = 0; c0 < nChunks; c0 += NSTAGE) {
        #pragma unroll
        for (int s = 0; s < NSTAGE; s++) {
            const int c = c0 + s;
            if (c < nChunks) {
                // oldest outstanding group (chunk c, slot s) is done
                asm volatile("cp.async.wait_group 3;" ::: "memory");

                // cc first: the ring-LDS second hop depends only on cc.y
                const float2 cc = stC[s][tid];
                const float4 a  = stA[s][tid];
                const float4 b  = stB[s][tid];

                // prefetch chunk c+4 into slot (s+4)%NSTAGE
                const int s4 = (s + NSTAGE - 1) % NSTAGE;
                const int tp = (c + NSTAGE - 1) * L + tid;
                if (on && tp < N_SAMPLES) {
                    cpa16(&stA[s4][tid], &g_A[tp]);
                    cpa16(&stB[s4][tid], &g_B[tp]);
                    cpa8 (&stC[s4][tid], &g_C[tp]);
                }
                asm volatile("cp.async.commit_group;" ::: "memory");

                const int t = c * L + tid;
                if (on && t < N_SAMPLES) {
                    const int BL = __float_as_int(cc.y);
                    float2 f0 = *reinterpret_cast<const float2*>(&ring[BL    ]);
                    float2 f1 = *reinterpret_cast<const float2*>(&ring[BL + 2]);
                    float2 f2 = *reinterpret_cast<const float2*>(&ring[BL + 4]);
                    float2 f3 = *reinterpret_cast<const float2*>(&ring[BL + 6]);
                    float m0 = fmaf(a.x, f0.x, a.y * f0.y);
                    float m1 = fmaf(a.z, f1.x, a.w * f1.y);
                    float m2 = fmaf(b.x, f2.x, b.y * f2.y);
                    float m3 = fmaf(b.z, f3.x, b.w * f3.y);
                    float y  = cc.x - ((m0 + m1) + (m2 + m3));
                    ring[slot] = y;
                    if (slot < 16) ring[slot + 1024] = y;   // seam replica
                    *outp = y;
                }
                __syncthreads();

                slot = (slot + L) & 1023;
                outp += L;
            }
        }
    }
}

// ---------------- launcher ----------------
extern "C" void kernel_launch(void* const* d_in, const int* in_sizes, int n_in,
                              void* d_out, int out_size)
{
    const float* delay     = (const float*)d_in[0];  // [128]
    const float* raw_gain  = (const float*)d_in[1];  // [1]
    const float* raw_coeff = (const float*)d_in[2];  // [128,6]
    const float* exc       = (const float*)d_in[3];  // [1,65536,1]
    const float* burst     = (const float*)d_in[4];  // [65536]
    float* out = (float*)d_out;

    prep_kernel<<<1, 256>>>(delay, raw_gain, raw_coeff);
    sample_kernel<<<N_SAMPLES / 256, 256>>>(exc, burst);
    exc_scan_kernel<<<1, 1>>>(exc, burst);
    ks_kernel<<<1, KS_THREADS>>>(out);
}

// round 16
// speedup vs baseline: 4.4065x; 3.2637x over previous
#include <cuda_runtime.h>
#include <math.h>

#define N_SAMPLES   65536
#define N_FRAMES    128
#define NUM_COEFF   6
#define NUM_ACTIVE  7
#define NSER        7
#define NSTAGE      5        // staging slots (4 cp.async groups in flight)
#define KS_THREADS  96       // 3 warps; L capped at 96 so all threads are active
#define SEG         2048
#define GRID_S      32       // SEG * GRID_S == N_SAMPLES

// ---------------- device scratch (no allocation allowed) ----------------
__device__ float  g_y[NSER][N_FRAMES];
__device__ float  g_M[NSER][N_FRAMES];
__device__ float4 g_A[N_SAMPLES];        // shifted weights w0..w3
__device__ float4 g_B[N_SAMPLES];        // shifted weights w4..w7
__device__ float2 g_C[N_SAMPLES];        // (x, bitcast LOW ring window base BL)
__device__ int    g_minz;
__device__ int    g_maxz;
__device__ int    g_flag;
__device__ int    g_maxsumbits;          // max over t of sum_k |v(t,k)|, as float bits

// ---------------- kernel A: coeff frames + spline tridiagonal solves -------
__global__ void prep_kernel(const float* __restrict__ delay,
                            const float* __restrict__ raw_gain,
                            const float* __restrict__ raw_coeff)
{
    __shared__ float s_y[NSER][N_FRAMES];
    __shared__ float s_cp[N_FRAMES];
    __shared__ float s_d[NSER][N_FRAMES];
    __shared__ float s_gain;

    const int tid = threadIdx.x;

    if (tid == 0) {
        s_gain = 1.0f / (1.0f + expf(-raw_gain[0]));
        g_minz = 0x7fffffff;
        g_maxz = 0;
        g_flag = 0;
        g_maxsumbits = 0;
        float c = 0.25f;
        s_cp[0] = c;
        for (int i = 1; i < N_FRAMES - 2; i++) {
            c = 1.0f / (4.0f - c);
            s_cp[i] = c;
        }
    }
    __syncthreads();

    for (int i = tid; i < N_FRAMES * NUM_COEFF; i += blockDim.x) {
        int r = i / NUM_COEFF, c = i % NUM_COEFF;
        s_y[1 + c][r] = 1.0f / (1.0f + expf(-raw_coeff[i]));
    }
    for (int r = tid; r < N_FRAMES; r += blockDim.x)
        s_y[0][r] = delay[r];
    __syncthreads();

    for (int r = tid; r < N_FRAMES; r += blockDim.x) {
        float sum = 0.0f;
        #pragma unroll
        for (int c = 0; c < NUM_COEFF; c++) sum += s_y[1 + c][r];
        float scale = s_gain / sum;
        #pragma unroll
        for (int c = 0; c < NUM_COEFF; c++) s_y[1 + c][r] *= scale;
    }
    __syncthreads();

    if (tid < NSER) {
        const int m = N_FRAMES - 2;
        const float K = 6.0f * 127.0f * 127.0f;
        float* y = s_y[tid];
        float* d = s_d[tid];

        float dp = K * (y[2] - 2.0f * y[1] + y[0]) * 0.25f;
        d[0] = dp;
        for (int i = 1; i < m; i++) {
            float rhs = K * (y[i + 2] - 2.0f * y[i + 1] + y[i]);
            dp = (rhs - dp) * s_cp[i];
            d[i] = dp;
        }
        g_M[tid][0] = 0.0f;
        g_M[tid][N_FRAMES - 1] = 0.0f;
        float Mn = 0.0f;
        for (int i = m - 1; i >= 0; i--) {
            Mn = d[i] - s_cp[i] * Mn;
            g_M[tid][i + 1] = Mn;
        }
    }
    __syncthreads();

    for (int i = tid; i < NSER * N_FRAMES; i += blockDim.x)
        (&g_y[0][0])[i] = (&s_y[0][0])[i];
}

// ---------------- kernel B: per-sample spline eval + SHIFTED tap weights ---
// (R15 format: aligned 8-float window in a 1040-entry seam-replicated ring;
//  BL = low base, weights shift-folded.)  Additionally records the global
// contraction factor max_t sum_k |v(t,k)| for the segmentation guard bound.
__global__ void sample_kernel(const float* __restrict__ exc,
                              const float* __restrict__ burst)
{
    const int t = blockIdx.x * blockDim.x + threadIdx.x;
    if (t >= N_SAMPLES) return;

    const float tt = (float)t * (1.0f / 65535.0f);
    int idx = (int)floorf(tt * 127.0f);
    idx = max(0, min(idx, 126));
    const float s  = tt - (float)idx * (1.0f / 127.0f);
    const float s2 = s * s;
    const float s3 = s2 * s;

    float vout[NSER];
    #pragma unroll
    for (int c = 0; c < NSER; c++) {
        float yi  = g_y[c][idx];
        float yi1 = g_y[c][idx + 1];
        float Mi  = g_M[c][idx];
        float Mi1 = g_M[c][idx + 1];
        float bsl = (yi1 - yi) * 127.0f - (2.0f * Mi + Mi1) * (1.0f / 762.0f);
        vout[c] = yi + bsl * s + 0.5f * Mi * s2 + (Mi1 - Mi) * s3 * (127.0f / 6.0f);
    }

    const float delay_i = vout[0];
    const int   z    = (int)floorf(delay_i);
    const float alfa = delay_i - (float)z;
    const float oma  = 1.0f - alfa;

    float v[7];
    v[0] = -oma * vout[1];
    #pragma unroll
    for (int k = 1; k < NUM_COEFF; k++)
        v[k] = -(alfa * vout[k] + oma * vout[k + 1]);
    v[6] = -alfa * vout[NUM_COEFF];

    float asum = 0.0f;
    #pragma unroll
    for (int k = 0; k < 7; k++) asum += fabsf(v[k]);

    const int pb = (t - 1 - z) & 1023;
    int q = pb - 6;
    if (q < 0) q += 1024;              // wrap-at-top window lands in tail replica
    const int d  = q & 1;
    const int BL = q & ~1;

    float w[8];
    #pragma unroll
    for (int i = 0; i < 8; i++) w[i] = 0.0f;
    #pragma unroll
    for (int k = 0; k < 7; k++) w[6 + d - k] = v[k];

    g_A[t] = make_float4(w[0], w[1], w[2], w[3]);
    g_B[t] = make_float4(w[4], w[5], w[6], w[7]);
    g_C[t] = make_float2(burst[t], __int_as_float(BL));

    if (exc[t] != 0.0f) atomicExch(&g_flag, 1);

    // warp reductions (positive float bits compare as ints)
    int wmin = __reduce_min_sync(0xffffffffu, z);
    int wmax = __reduce_max_sync(0xffffffffu, z);
    int wsum = __reduce_max_sync(0xffffffffu, __float_as_int(asum));
    if ((threadIdx.x & 31) == 0) {
        atomicMin(&g_minz, wmin);
        atomicMax(&g_maxz, wmax);
        atomicMax(&g_maxsumbits, wsum);
    }
}

// ---------------- kernel B2: general exc IIR fallback ----------------------
__global__ void exc_scan_kernel(const float* __restrict__ exc,
                                const float* __restrict__ burst)
{
    if (g_flag) {
        float ym1 = 0.0f;
        for (int t = 0; t < N_SAMPLES; t++) {
            ym1 = burst[t] - exc[t] * ym1;
            g_C[t].x = ym1;
        }
    }
}

// ---------------- cp.async helpers ----------------
__device__ __forceinline__ void cpa16(void* dst_smem, const void* src) {
    unsigned d = (unsigned)__cvta_generic_to_shared(dst_smem);
    asm volatile("cp.async.ca.shared.global [%0], [%1], 16;"
                 :: "r"(d), "l"(src) : "memory");
}
__device__ __forceinline__ void cpa8(void* dst_smem, const void* src) {
    unsigned d = (unsigned)__cvta_generic_to_shared(dst_smem);
    asm volatile("cp.async.ca.shared.global [%0], [%1], 8;"
                 :: "r"(d), "l"(src) : "memory");
}

// ---------------- kernel C: segmented chunk-parallel KS scan ---------------
// 32 CTAs, each the R15 champion loop over [t_start, t_end):
//   t_keep = cta*SEG, t_end = t_keep+SEG, t_start = max(0, t_keep - G).
// Guard G = n*(maxz+7) with n = ceil(ln(1e-6)/ln(ms)), ms = max_t sum|v| < 1
// (the recurrence is an L-inf contraction: any zero-init history error is
// multiplied by <= ms per feedback trip of <= maxz+7 samples, so after G
// guard samples the kept output's error is <= ~1e-6 relative).  CTA 0 is
// exact.  Deterministic fallback to single-CTA full scan if ms >= 0.97 or
// G > 14336.  Ring slot = global t mod 1024 => all precomputed window bases
// and the aliasing/zero-slot proofs carry over per-CTA unchanged (positions
// before t_start read never-yet-written slots: their first write is >= 711
// samples / >= 7 chunks after the last read, barrier-ordered).
__global__ void __launch_bounds__(KS_THREADS, 1) ks_kernel(float* __restrict__ out)
{
    __shared__ __align__(16) float ring[1056];
    __shared__ float4 stA[NSTAGE][KS_THREADS];
    __shared__ float4 stB[NSTAGE][KS_THREADS];
    __shared__ float2 stC[NSTAGE][KS_THREADS];
    __shared__ int    sL, sG, sFB;

    const int tid = threadIdx.x;
    #pragma unroll
    for (int i = tid; i < 1056; i += KS_THREADS) ring[i] = 0.0f;

    if (tid == 0) {
        int L = g_minz + 1;
        if (L > KS_THREADS) L = KS_THREADS;
        int cap = 1024 - (g_maxz + NUM_ACTIVE) - 1;
        if (L > cap) L = cap;
        if (L < 1)  L = 1;
        sL = L;

        float ms = __int_as_float(g_maxsumbits);
        int fb = 0, G = 0;
        if (!(ms > 0.0f) || ms >= 0.97f) {
            fb = 1;
        } else {
            float nf = 13.8155f / (-logf(ms));     // ln(1e-6)/ln(ms)
            int n = (int)ceilf(nf);
            if (n < 4) n = 4;
            G = n * (g_maxz + 7);
            if (G > 14336) fb = 1;
        }
        sG = G;
        sFB = fb;
    }
    __syncthreads();
    const int  L  = sL;
    const bool on = (tid < L);

    int t_keep, t_end;
    if (sFB) {
        if (blockIdx.x != 0) return;           // uniform CTA exit, no barriers yet
        t_keep = 0;
        t_end  = N_SAMPLES;
    } else {
        t_keep = blockIdx.x * SEG;
        t_end  = t_keep + SEG;
    }
    const int t_start = (t_keep - sG > 0) ? (t_keep - sG) : 0;
    const int nChunks = (t_end - t_start + L - 1) / L;

    // prologue: chunks 0..3 -> slots 0..3 (4 groups in flight)
    #pragma unroll
    for (int s = 0; s < NSTAGE - 1; s++) {
        const int t = t_start + s * L + tid;
        if (on && t < N_SAMPLES) {
            cpa16(&stA[s][tid], &g_A[t]);
            cpa16(&stB[s][tid], &g_B[t]);
            cpa8 (&stC[s][tid], &g_C[t]);
        }
        asm volatile("cp.async.commit_group;" ::: "memory");
    }

    int slot = (t_start + tid) & 1023;         // ring write slot

    for (int c0 = 0; c0 < nChunks; c0 += NSTAGE) {
        #pragma unroll
        for (int s = 0; s < NSTAGE; s++) {
            const int c = c0 + s;
            if (c < nChunks) {
                // oldest outstanding group (chunk c, slot s) is done
                asm volatile("cp.async.wait_group 3;" ::: "memory");

                // cc first: the ring-LDS second hop depends only on cc.y
                const float2 cc = stC[s][tid];
                const float4 a  = stA[s][tid];
                const float4 b  = stB[s][tid];

                // prefetch chunk c+4 into slot (s+4)%NSTAGE
                const int s4 = (s + NSTAGE - 1) % NSTAGE;
                const int tp = t_start + (c + NSTAGE - 1) * L + tid;
                if (on && tp < N_SAMPLES) {
                    cpa16(&stA[s4][tid], &g_A[tp]);
                    cpa16(&stB[s4][tid], &g_B[tp]);
                    cpa8 (&stC[s4][tid], &g_C[tp]);
                }
                asm volatile("cp.async.commit_group;" ::: "memory");

                const int t = t_start + c * L + tid;
                if (on && t < t_end) {
                    const int BL = __float_as_int(cc.y);
                    float2 f0 = *reinterpret_cast<const float2*>(&ring[BL    ]);
                    float2 f1 = *reinterpret_cast<const float2*>(&ring[BL + 2]);
                    float2 f2 = *reinterpret_cast<const float2*>(&ring[BL + 4]);
                    float2 f3 = *reinterpret_cast<const float2*>(&ring[BL + 6]);
                    float m0 = fmaf(a.x, f0.x, a.y * f0.y);
                    float m1 = fmaf(a.z, f1.x, a.w * f1.y);
                    float m2 = fmaf(b.x, f2.x, b.y * f2.y);
                    float m3 = fmaf(b.z, f3.x, b.w * f3.y);
                    float y  = cc.x - ((m0 + m1) + (m2 + m3));
                    ring[slot] = y;
                    if (slot < 16) ring[slot + 1024] = y;   // seam replica
                    if (t >= t_keep) out[t] = y;
                }
                __syncthreads();

                slot = (slot + L) & 1023;
            }
        }
    }
}

// ---------------- launcher ----------------
extern "C" void kernel_launch(void* const* d_in, const int* in_sizes, int n_in,
                              void* d_out, int out_size)
{
    const float* delay     = (const float*)d_in[0];  // [128]
    const float* raw_gain  = (const float*)d_in[1];  // [1]
    const float* raw_coeff = (const float*)d_in[2];  // [128,6]
    const float* exc       = (const float*)d_in[3];  // [1,65536,1]
    const float* burst     = (const float*)d_in[4];  // [65536]
    float* out = (float*)d_out;

    prep_kernel<<<1, 256>>>(delay, raw_gain, raw_coeff);
    sample_kernel<<<N_SAMPLES / 256, 256>>>(exc, burst);
    exc_scan_kernel<<<1, 1>>>(exc, burst);
    ks_kernel<<<GRID_S, KS_THREADS>>>(out);
}

// round 17
// speedup vs baseline: 4.4351x; 1.0065x over previous
#include <cuda_runtime.h>
#include <math.h>

#define N_SAMPLES   65536
#define N_FRAMES    128
#define NUM_COEFF   6
#define NUM_ACTIVE  7
#define NSER        7
#define NSTAGE      5        // staging slots (4 cp.async groups in flight)
#define KS_THREADS  96       // 3 warps; L capped at 96 so all threads are active
#define SEG         2048
#define GRID_S      32       // SEG * GRID_S == N_SAMPLES

// ---------------- device scratch (no allocation allowed) ----------------
__device__ float  g_y[NSER][N_FRAMES];
__device__ float  g_M[NSER][N_FRAMES];
__device__ float4 g_A[N_SAMPLES];        // shifted weights w0..w3
__device__ float4 g_B[N_SAMPLES];        // shifted weights w4..w7
__device__ float2 g_C[N_SAMPLES];        // (x, bitcast LOW ring window base BL)
__device__ int    g_minz;
__device__ int    g_maxz;
__device__ int    g_flag;
__device__ int    g_maxsumbits;          // max over t of sum_k |v(t,k)|, as float bits

// ---------------- kernel A: coeff frames + spline tridiagonal solves -------
__global__ void prep_kernel(const float* __restrict__ delay,
                            const float* __restrict__ raw_gain,
                            const float* __restrict__ raw_coeff)
{
    __shared__ float s_y[NSER][N_FRAMES];
    __shared__ float s_cp[N_FRAMES];
    __shared__ float s_d[NSER][N_FRAMES];
    __shared__ float s_gain;

    const int tid = threadIdx.x;

    if (tid == 0) {
        s_gain = 1.0f / (1.0f + expf(-raw_gain[0]));
        g_minz = 0x7fffffff;
        g_maxz = 0;
        g_flag = 0;
        g_maxsumbits = 0;
        float c = 0.25f;
        s_cp[0] = c;
        for (int i = 1; i < N_FRAMES - 2; i++) {
            c = 1.0f / (4.0f - c);
            s_cp[i] = c;
        }
    }
    __syncthreads();

    for (int i = tid; i < N_FRAMES * NUM_COEFF; i += blockDim.x) {
        int r = i / NUM_COEFF, c = i % NUM_COEFF;
        s_y[1 + c][r] = 1.0f / (1.0f + expf(-raw_coeff[i]));
    }
    for (int r = tid; r < N_FRAMES; r += blockDim.x)
        s_y[0][r] = delay[r];
    __syncthreads();

    for (int r = tid; r < N_FRAMES; r += blockDim.x) {
        float sum = 0.0f;
        #pragma unroll
        for (int c = 0; c < NUM_COEFF; c++) sum += s_y[1 + c][r];
        float scale = s_gain / sum;
        #pragma unroll
        for (int c = 0; c < NUM_COEFF; c++) s_y[1 + c][r] *= scale;
    }
    __syncthreads();

    if (tid < NSER) {
        const int m = N_FRAMES - 2;
        const float K = 6.0f * 127.0f * 127.0f;
        float* y = s_y[tid];
        float* d = s_d[tid];

        float dp = K * (y[2] - 2.0f * y[1] + y[0]) * 0.25f;
        d[0] = dp;
        for (int i = 1; i < m; i++) {
            float rhs = K * (y[i + 2] - 2.0f * y[i + 1] + y[i]);
            dp = (rhs - dp) * s_cp[i];
            d[i] = dp;
        }
        g_M[tid][0] = 0.0f;
        g_M[tid][N_FRAMES - 1] = 0.0f;
        float Mn = 0.0f;
        for (int i = m - 1; i >= 0; i--) {
            Mn = d[i] - s_cp[i] * Mn;
            g_M[tid][i + 1] = Mn;
        }
    }
    __syncthreads();

    for (int i = tid; i < NSER * N_FRAMES; i += blockDim.x)
        (&g_y[0][0])[i] = (&s_y[0][0])[i];
}

// ---------------- kernel B: per-sample spline eval + SHIFTED tap weights ---
// (R15 format: aligned 8-float window in a 1040-entry seam-replicated ring;
//  BL = low base, weights shift-folded.)  Additionally records the global
// contraction factor max_t sum_k |v(t,k)| for the segmentation guard bound.
__global__ void sample_kernel(const float* __restrict__ exc,
                              const float* __restrict__ burst)
{
    const int t = blockIdx.x * blockDim.x + threadIdx.x;
    if (t >= N_SAMPLES) return;

    const float tt = (float)t * (1.0f / 65535.0f);
    int idx = (int)floorf(tt * 127.0f);
    idx = max(0, min(idx, 126));
    const float s  = tt - (float)idx * (1.0f / 127.0f);
    const float s2 = s * s;
    const float s3 = s2 * s;

    float vout[NSER];
    #pragma unroll
    for (int c = 0; c < NSER; c++) {
        float yi  = g_y[c][idx];
        float yi1 = g_y[c][idx + 1];
        float Mi  = g_M[c][idx];
        float Mi1 = g_M[c][idx + 1];
        float bsl = (yi1 - yi) * 127.0f - (2.0f * Mi + Mi1) * (1.0f / 762.0f);
        vout[c] = yi + bsl * s + 0.5f * Mi * s2 + (Mi1 - Mi) * s3 * (127.0f / 6.0f);
    }

    const float delay_i = vout[0];
    const int   z    = (int)floorf(delay_i);
    const float alfa = delay_i - (float)z;
    const float oma  = 1.0f - alfa;

    float v[7];
    v[0] = -oma * vout[1];
    #pragma unroll
    for (int k = 1; k < NUM_COEFF; k++)
        v[k] = -(alfa * vout[k] + oma * vout[k + 1]);
    v[6] = -alfa * vout[NUM_COEFF];

    float asum = 0.0f;
    #pragma unroll
    for (int k = 0; k < 7; k++) asum += fabsf(v[k]);

    const int pb = (t - 1 - z) & 1023;
    int q = pb - 6;
    if (q < 0) q += 1024;              // wrap-at-top window lands in tail replica
    const int d  = q & 1;
    const int BL = q & ~1;

    float w[8];
    #pragma unroll
    for (int i = 0; i < 8; i++) w[i] = 0.0f;
    #pragma unroll
    for (int k = 0; k < 7; k++) w[6 + d - k] = v[k];

    g_A[t] = make_float4(w[0], w[1], w[2], w[3]);
    g_B[t] = make_float4(w[4], w[5], w[6], w[7]);
    g_C[t] = make_float2(burst[t], __int_as_float(BL));

    if (exc[t] != 0.0f) atomicExch(&g_flag, 1);

    // warp reductions (positive float bits compare as ints)
    int wmin = __reduce_min_sync(0xffffffffu, z);
    int wmax = __reduce_max_sync(0xffffffffu, z);
    int wsum = __reduce_max_sync(0xffffffffu, __float_as_int(asum));
    if ((threadIdx.x & 31) == 0) {
        atomicMin(&g_minz, wmin);
        atomicMax(&g_maxz, wmax);
        atomicMax(&g_maxsumbits, wsum);
    }
}

// ---------------- kernel B2: general exc IIR fallback ----------------------
__global__ void exc_scan_kernel(const float* __restrict__ exc,
                                const float* __restrict__ burst)
{
    if (g_flag) {
        float ym1 = 0.0f;
        for (int t = 0; t < N_SAMPLES; t++) {
            ym1 = burst[t] - exc[t] * ym1;
            g_C[t].x = ym1;
        }
    }
}

// ---------------- cp.async helpers ----------------
__device__ __forceinline__ void cpa16(void* dst_smem, const void* src) {
    unsigned d = (unsigned)__cvta_generic_to_shared(dst_smem);
    asm volatile("cp.async.ca.shared.global [%0], [%1], 16;"
                 :: "r"(d), "l"(src) : "memory");
}
__device__ __forceinline__ void cpa8(void* dst_smem, const void* src) {
    unsigned d = (unsigned)__cvta_generic_to_shared(dst_smem);
    asm volatile("cp.async.ca.shared.global [%0], [%1], 8;"
                 :: "r"(d), "l"(src) : "memory");
}

// ---------------- kernel C: segmented chunk-parallel KS scan ---------------
// 32 CTAs, each the R15 champion loop over [t_start, t_end):
//   t_keep = cta*SEG, t_end = t_keep+SEG, t_start = max(0, t_keep - G).
// Guard G = n*(maxz+7) with n = ceil(ln(1e-6)/ln(ms)), ms = max_t sum|v| < 1
// (the recurrence is an L-inf contraction: any zero-init history error is
// multiplied by <= ms per feedback trip of <= maxz+7 samples, so after G
// guard samples the kept output's error is <= ~1e-6 relative).  CTA 0 is
// exact.  Deterministic fallback to single-CTA full scan if ms >= 0.97 or
// G > 14336.  Ring slot = global t mod 1024 => all precomputed window bases
// and the aliasing/zero-slot proofs carry over per-CTA unchanged (positions
// before t_start read never-yet-written slots: their first write is >= 711
// samples / >= 7 chunks after the last read, barrier-ordered).
__global__ void __launch_bounds__(KS_THREADS, 1) ks_kernel(float* __restrict__ out)
{
    __shared__ __align__(16) float ring[1056];
    __shared__ float4 stA[NSTAGE][KS_THREADS];
    __shared__ float4 stB[NSTAGE][KS_THREADS];
    __shared__ float2 stC[NSTAGE][KS_THREADS];
    __shared__ int    sL, sG, sFB;

    const int tid = threadIdx.x;
    #pragma unroll
    for (int i = tid; i < 1056; i += KS_THREADS) ring[i] = 0.0f;

    if (tid == 0) {
        int L = g_minz + 1;
        if (L > KS_THREADS) L = KS_THREADS;
        int cap = 1024 - (g_maxz + NUM_ACTIVE) - 1;
        if (L > cap) L = cap;
        if (L < 1)  L = 1;
        sL = L;

        float ms = __int_as_float(g_maxsumbits);
        int fb = 0, G = 0;
        if (!(ms > 0.0f) || ms >= 0.97f) {
            fb = 1;
        } else {
            float nf = 13.8155f / (-logf(ms));     // ln(1e-6)/ln(ms)
            int n = (int)ceilf(nf);
            if (n < 4) n = 4;
            G = n * (g_maxz + 7);
            if (G > 14336) fb = 1;
        }
        sG = G;
        sFB = fb;
    }
    __syncthreads();
    const int  L  = sL;
    const bool on = (tid < L);

    int t_keep, t_end;
    if (sFB) {
        if (blockIdx.x != 0) return;           // uniform CTA exit, no barriers yet
        t_keep = 0;
        t_end  = N_SAMPLES;
    } else {
        t_keep = blockIdx.x * SEG;
        t_end  = t_keep + SEG;
    }
    const int t_start = (t_keep - sG > 0) ? (t_keep - sG) : 0;
    const int nChunks = (t_end - t_start + L - 1) / L;

    // prologue: chunks 0..3 -> slots 0..3 (4 groups in flight)
    #pragma unroll
    for (int s = 0; s < NSTAGE - 1; s++) {
        const int t = t_start + s * L + tid;
        if (on && t < N_SAMPLES) {
            cpa16(&stA[s][tid], &g_A[t]);
            cpa16(&stB[s][tid], &g_B[t]);
            cpa8 (&stC[s][tid], &g_C[t]);
        }
        asm volatile("cp.async.commit_group;" ::: "memory");
    }

    int slot = (t_start + tid) & 1023;         // ring write slot

    for (int c0 = 0; c0 < nChunks; c0 += NSTAGE) {
        #pragma unroll
        for (int s = 0; s < NSTAGE; s++) {
            const int c = c0 + s;
            if (c < nChunks) {
                // oldest outstanding group (chunk c, slot s) is done
                asm volatile("cp.async.wait_group 3;" ::: "memory");

                // cc first: the ring-LDS second hop depends only on cc.y
                const float2 cc = stC[s][tid];
                const float4 a  = stA[s][tid];
                const float4 b  = stB[s][tid];

                // prefetch chunk c+4 into slot (s+4)%NSTAGE
                const int s4 = (s + NSTAGE - 1) % NSTAGE;
                const int tp = t_start + (c + NSTAGE - 1) * L + tid;
                if (on && tp < N_SAMPLES) {
                    cpa16(&stA[s4][tid], &g_A[tp]);
                    cpa16(&stB[s4][tid], &g_B[tp]);
                    cpa8 (&stC[s4][tid], &g_C[tp]);
                }
                asm volatile("cp.async.commit_group;" ::: "memory");

                const int t = t_start + c * L + tid;
                if (on && t < t_end) {
                    const int BL = __float_as_int(cc.y);
                    float2 f0 = *reinterpret_cast<const float2*>(&ring[BL    ]);
                    float2 f1 = *reinterpret_cast<const float2*>(&ring[BL + 2]);
                    float2 f2 = *reinterpret_cast<const float2*>(&ring[BL + 4]);
                    float2 f3 = *reinterpret_cast<const float2*>(&ring[BL + 6]);
                    float m0 = fmaf(a.x, f0.x, a.y * f0.y);
                    float m1 = fmaf(a.z, f1.x, a.w * f1.y);
                    float m2 = fmaf(b.x, f2.x, b.y * f2.y);
                    float m3 = fmaf(b.z, f3.x, b.w * f3.y);
                    float y  = cc.x - ((m0 + m1) + (m2 + m3));
                    ring[slot] = y;
                    if (slot < 16) ring[slot + 1024] = y;   // seam replica
                    if (t >= t_keep) out[t] = y;
                }
                __syncthreads();

                slot = (slot + L) & 1023;
            }
        }
    }
}

// ---------------- launcher ----------------
extern "C" void kernel_launch(void* const* d_in, const int* in_sizes, int n_in,
                              void* d_out, int out_size)
{
    const float* delay     = (const float*)d_in[0];  // [128]
    const float* raw_gain  = (const float*)d_in[1];  // [1]
    const float* raw_coeff = (const float*)d_in[2];  // [128,6]
    const float* exc       = (const float*)d_in[3];  // [1,65536,1]
    const float* burst     = (const float*)d_in[4];  // [65536]
    float* out = (float*)d_out;

    prep_kernel<<<1, 256>>>(delay, raw_gain, raw_coeff);
    sample_kernel<<<N_SAMPLES / 256, 256>>>(exc, burst);
    exc_scan_kernel<<<1, 1>>>(exc, burst);
    ks_kernel<<<GRID_S, KS_THREADS>>>(out);
}